// round 5
// baseline (speedup 1.0000x reference)
#include <cuda_runtime.h>

// Problem constants (fixed by setup_inputs)
#define BB 16
#define HH 2048
#define WW 2048
#define SS 5000
#define NST (BB * SS)          // 80000 stations

#define THREADS 256
#define NBLK ((NST + THREADS - 1) / THREADS)   // 313

// Scratch for deterministic single-kernel reduction (no device mallocs allowed)
__device__ float g_partials[NBLK];
__device__ int   g_count = 0;   // self-resetting completion counter

// Select element r (0..3) from the 4-float window {a.x, a.y, b.x, b.y}.
__device__ __forceinline__ float sel4(float2 a, float2 b, int r)
{
    const float lo = (r & 1) ? a.y : a.x;
    const float hi = (r & 1) ? b.y : b.x;
    return (r & 2) ? hi : lo;
}

__global__ __launch_bounds__(THREADS, 2)
void station_loss_fused_kernel(const float* __restrict__ pred,
                               const int*   __restrict__ pos,
                               const float* __restrict__ runoff,
                               float*       __restrict__ out)
{
    const int tid = blockIdx.x * blockDim.x + threadIdx.x;

    float per_station = 0.0f;
    if (tid < NST) {
        const int b = tid / SS;
        const int2 pxy = __ldg((const int2*)pos + tid);  // .x = px (width), .y = py (height)
        const int x = pxy.x;
        const int y = pxy.y;
        const float* __restrict__ p = pred + (long long)b * (HH * WW);

        // Column window: two float2 loads starting at even xa cover
        // {clamp(x-1), x, clamp(x+1)} (interior: x-1-xa in {0,1} => x+1 <= xa+3).
        int xa = max(x - 1, 0);
        xa = min(xa, WW - 4);
        xa &= ~1;

        const int ym1 = max(y - 1, 0);
        const int yp1 = min(y + 1, HH - 1);

        const float* r0 = p + ym1 * WW + xa;
        const float* r1 = p + y   * WW + xa;
        const float* r2 = p + yp1 * WW + xa;

        // Front-batch all 7 loads for max MLP.
        const float2 a0 = __ldg((const float2*)(r0));
        const float2 b0 = __ldg((const float2*)(r0 + 2));
        const float2 a1 = __ldg((const float2*)(r1));
        const float2 b1 = __ldg((const float2*)(r1 + 2));
        const float2 a2 = __ldg((const float2*)(r2));
        const float2 b2 = __ldg((const float2*)(r2 + 2));
        const float  ro = __ldg(runoff + tid);

        // Relative column indices within the 4-float window.
        const int xm1 = max(x - 1, 0);
        const int xp1 = min(x + 1, WW - 1);
        const int rA = xm1 - xa;
        const int rB = x   - xa;
        const int rC = xp1 - xa;

        // Separable validity: mask = colflag x rowflag (rank-1).
        const float f0 = (x - 1 >= 0) ? 1.0f : 0.0f;
        const float f2 = (x + 1 < WW) ? 1.0f : 0.0f;
        const float g0 = (y - 1 >= 0) ? 1.0f : 0.0f;
        const float g2 = (y + 1 < HH) ? 1.0f : 0.0f;
        const float cnt = (1.0f + f0 + f2) * (1.0f + g0 + g2);

        const float s0 = f0 * sel4(a0, b0, rA) + sel4(a0, b0, rB) + f2 * sel4(a0, b0, rC);
        const float s1 = f0 * sel4(a1, b1, rA) + sel4(a1, b1, rB) + f2 * sel4(a1, b1, rC);
        const float s2 = f0 * sel4(a2, b2, rA) + sel4(a2, b2, rB) + f2 * sel4(a2, b2, rC);

        const float sum  = g0 * s0 + s1 + g2 * s2;
        const float avg  = sum / cnt;
        const float diff = avg - ro;
        per_station = diff * diff;
    }

    // Deterministic block reduction: warp shuffle then shared-mem tree.
    __shared__ float smem[THREADS / 32];
    float v = per_station;
    #pragma unroll
    for (int off = 16; off > 0; off >>= 1)
        v += __shfl_down_sync(0xFFFFFFFFu, v, off);
    const int lane = threadIdx.x & 31;
    const int warp = threadIdx.x >> 5;
    if (lane == 0) smem[warp] = v;
    __syncthreads();

    // Warp 0 finishes the block sum, publishes it, and (if it is the last
    // block to finish) performs the whole final reduction alone. No extra
    // block-wide sync, no smem broadcast -> minimal perturbation of the
    // gather code above.
    if (warp == 0) {
        v = (lane < THREADS / 32) ? smem[lane] : 0.0f;
        #pragma unroll
        for (int off = 16; off > 0; off >>= 1)
            v += __shfl_down_sync(0xFFFFFFFFu, v, off);

        int is_last = 0;
        if (lane == 0) {
            g_partials[blockIdx.x] = v;
            __threadfence();                       // publish partial before tick
            is_last = (atomicAdd(&g_count, 1) == NBLK - 1);
        }
        is_last = __shfl_sync(0xFFFFFFFFu, is_last, 0);

        if (is_last) {
            __threadfence();                       // acquire all partials
            float s = 0.0f;
            #pragma unroll 4
            for (int i = lane; i < NBLK; i += 32)
                s += __ldcg(&g_partials[i]);       // L2-coherent loads, fixed order
            #pragma unroll
            for (int off = 16; off > 0; off >>= 1)
                s += __shfl_down_sync(0xFFFFFFFFu, s, off);
            if (lane == 0) {
                out[0] = s / (float)NST;
                g_count = 0;                       // reset for next graph replay
            }
        }
    }
}

extern "C" void kernel_launch(void* const* d_in, const int* in_sizes, int n_in,
                              void* d_out, int out_size)
{
    const float* pred   = (const float*)d_in[0];  // (16,1,2048,2048) f32
    const int*   pos    = (const int*)  d_in[1];  // (16,5000,2) i32
    const float* runoff = (const float*)d_in[2];  // (16,5000) f32
    float* out = (float*)d_out;

    station_loss_fused_kernel<<<NBLK, THREADS>>>(pred, pos, runoff, out);
}

// round 6
// speedup vs baseline: 1.1607x; 1.1607x over previous
#include <cuda_runtime.h>

// Problem constants (fixed by setup_inputs)
#define BB 16
#define HH 2048
#define WW 2048
#define SS 5000
#define NST (BB * SS)          // 80000 stations

#define THREADS 256
#define NBLK ((NST + THREADS - 1) / THREADS)   // 313

#define RTHREADS 512

// Scratch for deterministic two-stage reduction (no device mallocs allowed)
__device__ float g_partials[NBLK];

// Select element r (0..3) from the 4-float window {a.x, a.y, b.x, b.y}.
__device__ __forceinline__ float sel4(float2 a, float2 b, int r)
{
    const float lo = (r & 1) ? a.y : a.x;
    const float hi = (r & 1) ? b.y : b.x;
    return (r & 2) ? hi : lo;
}

__global__ __launch_bounds__(THREADS)
void station_loss_kernel(const float* __restrict__ pred,
                         const int*   __restrict__ pos,
                         const float* __restrict__ runoff)
{
    // Allow the dependent (reduce) kernel to begin launching/ramping NOW.
    // Its griddepcontrol.wait still blocks until this grid completes and
    // flushes memory, so g_partials is safe.
    asm volatile("griddepcontrol.launch_dependents;" ::: "memory");

    const int tid = blockIdx.x * blockDim.x + threadIdx.x;

    float per_station = 0.0f;
    if (tid < NST) {
        const int b = tid / SS;
        const int2 pxy = __ldg((const int2*)pos + tid);  // .x = px (width), .y = py (height)
        const int x = pxy.x;
        const int y = pxy.y;
        const float* __restrict__ p = pred + (long long)b * (HH * WW);

        // Column window: two float2 loads starting at even xa cover
        // {clamp(x-1), x, clamp(x+1)} (interior: x-1-xa in {0,1} => x+1 <= xa+3).
        int xa = max(x - 1, 0);
        xa = min(xa, WW - 4);
        xa &= ~1;

        const int ym1 = max(y - 1, 0);
        const int yp1 = min(y + 1, HH - 1);

        const float* r0 = p + ym1 * WW + xa;
        const float* r1 = p + y   * WW + xa;
        const float* r2 = p + yp1 * WW + xa;

        // Front-batch all 7 loads for max MLP.
        const float2 a0 = __ldg((const float2*)(r0));
        const float2 b0 = __ldg((const float2*)(r0 + 2));
        const float2 a1 = __ldg((const float2*)(r1));
        const float2 b1 = __ldg((const float2*)(r1 + 2));
        const float2 a2 = __ldg((const float2*)(r2));
        const float2 b2 = __ldg((const float2*)(r2 + 2));
        const float  ro = __ldg(runoff + tid);

        // Relative column indices within the 4-float window.
        const int xm1 = max(x - 1, 0);
        const int xp1 = min(x + 1, WW - 1);
        const int rA = xm1 - xa;
        const int rB = x   - xa;
        const int rC = xp1 - xa;

        // Separable validity: mask = colflag x rowflag (rank-1).
        const float f0 = (x - 1 >= 0) ? 1.0f : 0.0f;
        const float f2 = (x + 1 < WW) ? 1.0f : 0.0f;
        const float g0 = (y - 1 >= 0) ? 1.0f : 0.0f;
        const float g2 = (y + 1 < HH) ? 1.0f : 0.0f;
        const float cnt = (1.0f + f0 + f2) * (1.0f + g0 + g2);

        const float s0 = f0 * sel4(a0, b0, rA) + sel4(a0, b0, rB) + f2 * sel4(a0, b0, rC);
        const float s1 = f0 * sel4(a1, b1, rA) + sel4(a1, b1, rB) + f2 * sel4(a1, b1, rC);
        const float s2 = f0 * sel4(a2, b2, rA) + sel4(a2, b2, rB) + f2 * sel4(a2, b2, rC);

        const float sum  = g0 * s0 + s1 + g2 * s2;
        const float avg  = sum / cnt;
        const float diff = avg - ro;
        per_station = diff * diff;
    }

    // Deterministic block reduction: warp shuffle then shared-mem tree.
    __shared__ float smem[THREADS / 32];
    float v = per_station;
    #pragma unroll
    for (int off = 16; off > 0; off >>= 1)
        v += __shfl_down_sync(0xFFFFFFFFu, v, off);
    const int lane = threadIdx.x & 31;
    const int warp = threadIdx.x >> 5;
    if (lane == 0) smem[warp] = v;
    __syncthreads();
    if (warp == 0) {
        v = (lane < THREADS / 32) ? smem[lane] : 0.0f;
        #pragma unroll
        for (int off = 16; off > 0; off >>= 1)
            v += __shfl_down_sync(0xFFFFFFFFu, v, off);
        if (lane == 0) g_partials[blockIdx.x] = v;
    }
}

__global__ __launch_bounds__(RTHREADS)
void final_reduce_kernel(float* __restrict__ out)
{
    // PDL: we were allowed to launch early; block here until the gather grid
    // has completed and its memory is visible.
    asm volatile("griddepcontrol.wait;" ::: "memory");

    __shared__ float smem[RTHREADS / 32];
    float s = 0.0f;
    for (int i = threadIdx.x; i < NBLK; i += RTHREADS)
        s += g_partials[i];
    #pragma unroll
    for (int off = 16; off > 0; off >>= 1)
        s += __shfl_down_sync(0xFFFFFFFFu, s, off);
    const int lane = threadIdx.x & 31;
    const int warp = threadIdx.x >> 5;
    if (lane == 0) smem[warp] = s;
    __syncthreads();
    if (warp == 0) {
        s = (lane < RTHREADS / 32) ? smem[lane] : 0.0f;
        #pragma unroll
        for (int off = 16; off > 0; off >>= 1)
            s += __shfl_down_sync(0xFFFFFFFFu, s, off);
        if (lane == 0) out[0] = s / (float)NST;
    }
}

extern "C" void kernel_launch(void* const* d_in, const int* in_sizes, int n_in,
                              void* d_out, int out_size)
{
    const float* pred   = (const float*)d_in[0];  // (16,1,2048,2048) f32
    const int*   pos    = (const int*)  d_in[1];  // (16,5000,2) i32
    const float* runoff = (const float*)d_in[2];  // (16,5000) f32
    float* out = (float*)d_out;

    station_loss_kernel<<<NBLK, THREADS>>>(pred, pos, runoff);

    // Launch the reduce with Programmatic Dependent Launch so its launch
    // latency overlaps the gather kernel's execution.
    cudaLaunchConfig_t cfg = {};
    cfg.gridDim  = dim3(1, 1, 1);
    cfg.blockDim = dim3(RTHREADS, 1, 1);
    cfg.dynamicSmemBytes = 0;
    cfg.stream = 0;  // same (default) stream as the gather launch

    cudaLaunchAttribute attrs[1];
    attrs[0].id = cudaLaunchAttributeProgrammaticStreamSerialization;
    attrs[0].val.programmaticStreamSerializationAllowed = 1;
    cfg.attrs = attrs;
    cfg.numAttrs = 1;

    cudaLaunchKernelEx(&cfg, final_reduce_kernel, out);
}

// round 7
// speedup vs baseline: 1.2646x; 1.0895x over previous
#include <cuda_runtime.h>

// Problem constants (fixed by setup_inputs)
#define BB 16
#define HH 2048
#define WW 2048
#define SS 5000
#define NST (BB * SS)          // 80000 stations

#define THREADS 256
#define NBLK ((NST + THREADS - 1) / THREADS)   // 313

#define INV_NST (1.0f / (float)NST)

// Select element r (0..3) from the 4-float window {a.x, a.y, b.x, b.y}.
__device__ __forceinline__ float sel4(float2 a, float2 b, int r)
{
    const float lo = (r & 1) ? a.y : a.x;
    const float hi = (r & 1) ? b.y : b.x;
    return (r & 2) ? hi : lo;
}

__global__ __launch_bounds__(THREADS)
void station_loss_kernel(const float* __restrict__ pred,
                         const int*   __restrict__ pos,
                         const float* __restrict__ runoff,
                         float*       __restrict__ out)
{
    const int tid = blockIdx.x * blockDim.x + threadIdx.x;

    float per_station = 0.0f;
    if (tid < NST) {
        const int b = tid / SS;
        const int2 pxy = __ldg((const int2*)pos + tid);  // .x = px (width), .y = py (height)
        const int x = pxy.x;
        const int y = pxy.y;
        const float* __restrict__ p = pred + (long long)b * (HH * WW);

        // Column window: two float2 loads starting at even xa cover
        // {clamp(x-1), x, clamp(x+1)} (interior: x-1-xa in {0,1} => x+1 <= xa+3).
        int xa = max(x - 1, 0);
        xa = min(xa, WW - 4);
        xa &= ~1;

        const int ym1 = max(y - 1, 0);
        const int yp1 = min(y + 1, HH - 1);

        const float* r0 = p + ym1 * WW + xa;
        const float* r1 = p + y   * WW + xa;
        const float* r2 = p + yp1 * WW + xa;

        // Front-batch all 7 loads for max MLP.
        const float2 a0 = __ldg((const float2*)(r0));
        const float2 b0 = __ldg((const float2*)(r0 + 2));
        const float2 a1 = __ldg((const float2*)(r1));
        const float2 b1 = __ldg((const float2*)(r1 + 2));
        const float2 a2 = __ldg((const float2*)(r2));
        const float2 b2 = __ldg((const float2*)(r2 + 2));
        const float  ro = __ldg(runoff + tid);

        // Relative column indices within the 4-float window.
        const int xm1 = max(x - 1, 0);
        const int xp1 = min(x + 1, WW - 1);
        const int rA = xm1 - xa;
        const int rB = x   - xa;
        const int rC = xp1 - xa;

        // Separable validity: mask = colflag x rowflag (rank-1).
        const float f0 = (x - 1 >= 0) ? 1.0f : 0.0f;
        const float f2 = (x + 1 < WW) ? 1.0f : 0.0f;
        const float g0 = (y - 1 >= 0) ? 1.0f : 0.0f;
        const float g2 = (y + 1 < HH) ? 1.0f : 0.0f;
        const float cnt = (1.0f + f0 + f2) * (1.0f + g0 + g2);

        const float s0 = f0 * sel4(a0, b0, rA) + sel4(a0, b0, rB) + f2 * sel4(a0, b0, rC);
        const float s1 = f0 * sel4(a1, b1, rA) + sel4(a1, b1, rB) + f2 * sel4(a1, b1, rC);
        const float s2 = f0 * sel4(a2, b2, rA) + sel4(a2, b2, rB) + f2 * sel4(a2, b2, rC);

        const float sum  = g0 * s0 + s1 + g2 * s2;
        const float avg  = sum / cnt;
        const float diff = avg - ro;
        per_station = diff * diff;
    }

    // Deterministic block reduction: warp shuffle then shared-mem tree.
    __shared__ float smem[THREADS / 32];
    float v = per_station;
    #pragma unroll
    for (int off = 16; off > 0; off >>= 1)
        v += __shfl_down_sync(0xFFFFFFFFu, v, off);
    const int lane = threadIdx.x & 31;
    const int warp = threadIdx.x >> 5;
    if (lane == 0) smem[warp] = v;
    __syncthreads();
    if (warp == 0) {
        v = (lane < THREADS / 32) ? smem[lane] : 0.0f;
        #pragma unroll
        for (int off = 16; off > 0; off >>= 1)
            v += __shfl_down_sync(0xFFFFFFFFu, v, off);
        // Fire-and-forget global reduction: one RED.ADD.F32 per block.
        // d_out is zeroed by the leading memset node each replay.
        if (lane == 0) atomicAdd(out, v * INV_NST);
    }
}

extern "C" void kernel_launch(void* const* d_in, const int* in_sizes, int n_in,
                              void* d_out, int out_size)
{
    const float* pred   = (const float*)d_in[0];  // (16,1,2048,2048) f32
    const int*   pos    = (const int*)  d_in[1];  // (16,5000,2) i32
    const float* runoff = (const float*)d_in[2];  // (16,5000) f32
    float* out = (float*)d_out;

    // Zero the 4-byte accumulator (graph-capturable async memset node).
    cudaMemsetAsync(out, 0, sizeof(float), 0);

    station_loss_kernel<<<NBLK, THREADS>>>(pred, pos, runoff, out);
}